// round 3
// baseline (speedup 1.0000x reference)
#include <cuda_runtime.h>
#include <cuda_bf16.h>
#include <stdint.h>

// Problem constants
#define BB 4
#define HH 4
#define BH (BB*HH)          // 16
#define VV 8
#define NN 16384
#define FD 32
#define NC 32768            // 32*32*32
#define NE (VV*NN)          // entries per bh = 131072
#define NE_TOT (BH*NE)      // 2,097,152 total entries

// ---------------------------------------------------------------------------
// Scratch (device globals — no runtime allocation allowed)
// ---------------------------------------------------------------------------
__device__ float g_featsT[BH * NN * FD];   // 32 MB  [bh][n][f]
__device__ uint2 g_entries[NE_TOT];        // 16 MB  packed {n, bits(lc)}
__device__ int   g_count  [BH * NC];       // 2 MB
__device__ int   g_offsets[BH * NC];       // 2 MB   global exclusive offsets
__device__ int   g_cursor [BH * NC];       // 2 MB   mutable copy for scatter

// ---------------------------------------------------------------------------
// 0) zero the histogram counters (must happen every replay)
// ---------------------------------------------------------------------------
__global__ void zero_counts_kernel() {
    int i = blockIdx.x * blockDim.x + threadIdx.x;   // over int4 elements
    ((int4*)g_count)[i] = make_int4(0, 0, 0, 0);
}

// ---------------------------------------------------------------------------
// 1) transpose feats [bh][f][n] -> feats_T [bh][n][f]
// block (32,32); grid (NN/32, BH)
// ---------------------------------------------------------------------------
__global__ void transpose_kernel(const float* __restrict__ feats) {
    __shared__ float tile[32][33];
    const int bh = blockIdx.y;
    const int n0 = blockIdx.x * 32;
    const int tx = threadIdx.x, ty = threadIdx.y;
    // read: f = ty, n = n0+tx  (coalesced along n)
    tile[ty][tx] = feats[(bh * FD + ty) * NN + n0 + tx];
    __syncthreads();
    // write: n = n0+ty, f = tx  (coalesced along f)
    g_featsT[(bh * NN + n0 + ty) * FD + tx] = tile[tx][ty];
}

// ---------------------------------------------------------------------------
// 2) histogram of cell indices
// ---------------------------------------------------------------------------
__global__ void hist_kernel(const int* __restrict__ fidx) {
    int i = blockIdx.x * blockDim.x + threadIdx.x;   // 0..NE_TOT-1
    int bh = i / NE;
    int c  = fidx[i] & (NC - 1);
    atomicAdd(&g_count[bh * NC + c], 1);
}

// ---------------------------------------------------------------------------
// 3) per-bh exclusive scan of counts -> global offsets (+ cursor copy)
// 16 blocks x 1024 threads; each thread handles 32 cells
// ---------------------------------------------------------------------------
__global__ void scan_kernel() {
    const int bh = blockIdx.x;
    const int t  = threadIdx.x;
    const int base = bh * NC + t * 32;

    int local[32];
    int s = 0;
#pragma unroll
    for (int i = 0; i < 32; i++) { local[i] = g_count[base + i]; s += local[i]; }

    // block-wide exclusive scan of the 1024 per-thread sums
    const int lane = t & 31, w = t >> 5;
    int v = s;
#pragma unroll
    for (int d = 1; d < 32; d <<= 1) {
        int u = __shfl_up_sync(0xffffffffu, v, d);
        if (lane >= d) v += u;
    }
    __shared__ int wsum[32];
    if (lane == 31) wsum[w] = v;
    __syncthreads();
    if (w == 0) {
        int x = wsum[lane];
#pragma unroll
        for (int d = 1; d < 32; d <<= 1) {
            int u = __shfl_up_sync(0xffffffffu, x, d);
            if (lane >= d) x += u;
        }
        wsum[lane] = x;   // inclusive over warp totals
    }
    __syncthreads();

    int excl = (v - s) + (w > 0 ? wsum[w - 1] : 0) + bh * NE;  // global base
    int run = excl;
#pragma unroll
    for (int i = 0; i < 32; i++) {
        g_offsets[base + i] = run;
        g_cursor [base + i] = run;
        run += local[i];
    }
}

// ---------------------------------------------------------------------------
// 4) scatter entries into their cell buckets
// ---------------------------------------------------------------------------
__global__ void scatter_kernel(const float* __restrict__ lc,
                               const int* __restrict__ fidx) {
    int i = blockIdx.x * blockDim.x + threadIdx.x;   // 0..NE_TOT-1
    int bh = i / NE;
    int n  = i & (NN - 1);
    int c  = fidx[i] & (NC - 1);
    float l = lc[i];
    int pos = atomicAdd(&g_cursor[bh * NC + c], 1);
    g_entries[pos] = make_uint2((unsigned)n, __float_as_uint(l));
}

// ---------------------------------------------------------------------------
// 5) gather: one warp per cell, lane = feature channel
// block 1024 (32 warps = 32 consecutive cells); grid (NC/32, BH)
// out[bh][f][c] = max(0, max_entries feats_T[bh][n][f] * lc)
// ---------------------------------------------------------------------------
__global__ void gather_kernel(float* __restrict__ out) {
    __shared__ float tile[32][33];
    const int bh   = blockIdx.y;
    const int c0   = blockIdx.x * 32;
    const int lane = threadIdx.x & 31;     // = f
    const int w    = threadIdx.x >> 5;     // cell within tile
    const int bhc  = bh * NC + c0 + w;

    const int start = g_offsets[bhc];
    const int cnt   = g_count[bhc];
    const float* __restrict__ ft = g_featsT + (size_t)bh * NN * FD;

    float m = 0.f;
    for (int base = 0; base < cnt; base += 32) {
        const int rem = min(32, cnt - base);
        uint2 e = (lane < rem) ? g_entries[start + base + lane]
                               : make_uint2(0u, 0u);
        for (int j = 0; j < rem; j++) {
            const int   nj = (int)__shfl_sync(0xffffffffu, e.x, j);
            const float lj = __uint_as_float(__shfl_sync(0xffffffffu, e.y, j));
            const float fv = ft[nj * FD + lane];
            m = fmaxf(m, fv * lj);
        }
    }

    tile[lane][w] = m;      // tile[f][c_local]
    __syncthreads();

    // coalesced write: warp = one f-row, 32 consecutive cells
    const int f  = threadIdx.x >> 5;
    const int cl = threadIdx.x & 31;
    out[((size_t)bh * FD + f) * NC + c0 + cl] = tile[f][cl];
}

// ---------------------------------------------------------------------------
// kernel_launch
//   d_in[0] local_coordinate  float32 [B,H,V,N]
//   d_in[1] flattened_index   int32   [B,H,V,N]
//   d_in[2] features          float32 [B,128,N]
//   d_out   float32 [B,128,32,32,32]
// ---------------------------------------------------------------------------
extern "C" void kernel_launch(void* const* d_in, const int* in_sizes, int n_in,
                              void* d_out, int out_size) {
    const float* lc    = (const float*)d_in[0];
    const int*   fidx  = (const int*)d_in[1];
    const float* feats = (const float*)d_in[2];
    float*       out   = (float*)d_out;

    // 0) zero counters: BH*NC ints = 524288 -> 131072 int4
    zero_counts_kernel<<<(BH * NC / 4) / 256, 256>>>();

    // 1) transpose feats
    {
        dim3 block(32, 32), grid(NN / 32, BH);
        transpose_kernel<<<grid, block>>>(feats);
    }

    // 2) histogram
    hist_kernel<<<NE_TOT / 256, 256>>>(fidx);

    // 3) scan -> offsets
    scan_kernel<<<BH, 1024>>>();

    // 4) scatter entries
    scatter_kernel<<<NE_TOT / 256, 256>>>(lc, fidx);

    // 5) gather -> out
    {
        dim3 grid(NC / 32, BH);
        gather_kernel<<<grid, 1024>>>(out);
    }
}

// round 6
// speedup vs baseline: 1.2752x; 1.2752x over previous
#include <cuda_runtime.h>
#include <cuda_bf16.h>
#include <stdint.h>

// Problem constants
#define BB 4
#define HH 4
#define BH (BB*HH)          // 16
#define VV 8
#define NN 16384
#define FD 32
#define NC 32768            // 32*32*32
#define NE (VV*NN)          // entries per bh = 131072
#define NE_TOT (BH*NE)      // 2,097,152 total entries
#define KCAP 16             // bucket capacity (Poisson mean 4 -> ~1 expected overflow)
#define SPILL_CAP 8192

// ---------------------------------------------------------------------------
// Scratch (device globals — no runtime allocation allowed)
// ---------------------------------------------------------------------------
__device__ float g_featsT [BH * NN * FD];        // 32 MB  [bh][n][f]
__device__ uint2 g_entries[BH * NC * KCAP];      // 64 MB  {n, bits(lc)}
__device__ int   g_count  [BH * NC];             // 2 MB
__device__ uint4 g_spill  [SPILL_CAP];           // {bh, c, n, bits(lc)}
__device__ int   g_spill_cnt;

// ---------------------------------------------------------------------------
// 0) zero counters + spill counter (every replay)
// ---------------------------------------------------------------------------
__global__ void zero_counts_kernel() {
    int i = blockIdx.x * blockDim.x + threadIdx.x;   // over int4 elements
    ((int4*)g_count)[i] = make_int4(0, 0, 0, 0);
    if (i == 0) g_spill_cnt = 0;
}

// ---------------------------------------------------------------------------
// 1) transpose feats [bh][f][n] -> feats_T [bh][n][f]
// block (32,32); grid (NN/32, BH)
// ---------------------------------------------------------------------------
__global__ void transpose_kernel(const float* __restrict__ feats) {
    __shared__ float tile[32][33];
    const int bh = blockIdx.y;
    const int n0 = blockIdx.x * 32;
    const int tx = threadIdx.x, ty = threadIdx.y;
    tile[ty][tx] = feats[(bh * FD + ty) * NN + n0 + tx];   // coalesced in n
    __syncthreads();
    g_featsT[(bh * NN + n0 + ty) * FD + tx] = tile[tx][ty]; // coalesced in f
}

// ---------------------------------------------------------------------------
// 2) scatter entries into fixed-capacity buckets (single pass over inputs)
// ---------------------------------------------------------------------------
__global__ void scatter_kernel(const float* __restrict__ lc,
                               const int* __restrict__ fidx) {
    int i = blockIdx.x * blockDim.x + threadIdx.x;   // 0..NE_TOT-1
    int bh = i / NE;
    int n  = i & (NN - 1);
    int c  = fidx[i] & (NC - 1);
    float l = lc[i];
    int bhc = bh * NC + c;
    int pos = atomicAdd(&g_count[bhc], 1);
    if (pos < KCAP) {
        g_entries[bhc * KCAP + pos] = make_uint2((unsigned)n, __float_as_uint(l));
    } else {
        int sp = atomicAdd(&g_spill_cnt, 1);
        if (sp < SPILL_CAP)
            g_spill[sp] = make_uint4((unsigned)bh, (unsigned)c,
                                     (unsigned)n, __float_as_uint(l));
    }
}

// ---------------------------------------------------------------------------
// 3) gather: one warp per cell, lane = feature channel
// block 1024 (32 warps = 32 consecutive cells); grid (NC/32, BH)
// out[bh][f][c] = max(0, max_entries feats_T[bh][n][f] * lc)
// ---------------------------------------------------------------------------
__global__ void gather_kernel(float* __restrict__ out) {
    __shared__ float tile[32][33];
    const int bh   = blockIdx.y;
    const int c0   = blockIdx.x * 32;
    const int lane = threadIdx.x & 31;     // = f
    const int w    = threadIdx.x >> 5;     // cell within tile
    const int bhc  = bh * NC + c0 + w;

    const int cnt = min(g_count[bhc], KCAP);
    const float* __restrict__ ft = g_featsT + (size_t)bh * NN * FD;

    // one conditional entry load (cnt <= 16 <= 32)
    uint2 e = (lane < cnt) ? g_entries[bhc * KCAP + lane] : make_uint2(0u, 0u);

    float m = 0.f;
#pragma unroll 4
    for (int j = 0; j < cnt; j++) {
        const int   nj = (int)__shfl_sync(0xffffffffu, e.x, j);
        const float lj = __uint_as_float(__shfl_sync(0xffffffffu, e.y, j));
        const float fv = ft[nj * FD + lane];     // coalesced 128B row
        m = fmaxf(m, fv * lj);
    }

    tile[lane][w] = m;      // tile[f][c_local]
    __syncthreads();

    // coalesced write: warp = one f-row, 32 consecutive cells
    const int f  = threadIdx.x >> 5;
    const int cl = threadIdx.x & 31;
    out[((size_t)bh * FD + f) * NC + c0 + cl] = tile[f][cl];
}

// ---------------------------------------------------------------------------
// 4) spill: rare overflow entries -> atomicMax into out (after gather)
// single block, warp per entry, lane = f
// ---------------------------------------------------------------------------
__global__ void spill_kernel(float* __restrict__ out) {
    const int lane = threadIdx.x & 31;
    const int wid  = threadIdx.x >> 5;      // 8 warps
    const int cnt  = min(g_spill_cnt, SPILL_CAP);
    for (int s = wid; s < cnt; s += 8) {
        uint4 e = g_spill[s];
        const int bh = (int)e.x, c = (int)e.y, n = (int)e.z;
        const float l = __uint_as_float(e.w);
        const float fv = g_featsT[((size_t)bh * NN + n) * FD + lane];
        const float val = fv * l;
        if (val > 0.f)
            atomicMax((int*)out + ((size_t)bh * FD + lane) * NC + c,
                      __float_as_int(val));
    }
}

// ---------------------------------------------------------------------------
// kernel_launch
//   d_in[0] local_coordinate  float32 [B,H,V,N]
//   d_in[1] flattened_index   int32   [B,H,V,N]
//   d_in[2] features          float32 [B,128,N]
//   d_out   float32 [B,128,32,32,32]
// ---------------------------------------------------------------------------
extern "C" void kernel_launch(void* const* d_in, const int* in_sizes, int n_in,
                              void* d_out, int out_size) {
    const float* lc    = (const float*)d_in[0];
    const int*   fidx  = (const int*)d_in[1];
    const float* feats = (const float*)d_in[2];
    float*       out   = (float*)d_out;

    // 0) zero counters: BH*NC ints = 524288 -> 131072 int4
    zero_counts_kernel<<<(BH * NC / 4) / 256, 256>>>();

    // 1) transpose feats
    {
        dim3 block(32, 32), grid(NN / 32, BH);
        transpose_kernel<<<grid, block>>>(feats);
    }

    // 2) scatter into buckets
    scatter_kernel<<<NE_TOT / 256, 256>>>(lc, fidx);

    // 3) gather -> out (writes every cell; no zero-out needed)
    {
        dim3 grid(NC / 32, BH);
        gather_kernel<<<grid, 1024>>>(out);
    }

    // 4) rare spills
    spill_kernel<<<1, 256>>>(out);
}

// round 7
// speedup vs baseline: 1.7037x; 1.3360x over previous
#include <cuda_runtime.h>
#include <cuda_bf16.h>
#include <stdint.h>

// Problem constants
#define BB 4
#define HH 4
#define BH (BB*HH)          // 16
#define VV 8
#define NN 16384
#define FD 32
#define NC 32768            // 32*32*32
#define NE (VV*NN)          // entries per bh = 131072
#define NE_TOT (BH*NE)      // 2,097,152 total entries
#define KCAP 8              // bucket capacity (Poisson mean 4)
#define SPILL_CAP 65536
#define CPB 64              // cells per gather block

// ---------------------------------------------------------------------------
// Scratch (device globals — no runtime allocation allowed)
// ---------------------------------------------------------------------------
__device__ float g_featsT [BH * NN * FD];        // 32 MB [bh][n][f]
__device__ uint2 g_entries[BH * NC * KCAP];      // 32 MB {n, bits(lc)}
__device__ int   g_count  [BH * NC];             // 2 MB
__device__ uint4 g_spill  [SPILL_CAP];           // {bh, c, n, bits(lc)}
__device__ int   g_spill_cnt;

// ---------------------------------------------------------------------------
// 0) zero counters + spill counter
// ---------------------------------------------------------------------------
__global__ void zero_counts_kernel() {
    int i = blockIdx.x * blockDim.x + threadIdx.x;   // over int4 elements
    ((int4*)g_count)[i] = make_int4(0, 0, 0, 0);
    if (i == 0) g_spill_cnt = 0;
}

// ---------------------------------------------------------------------------
// 1) transpose feats [bh][f][n] -> feats_T [bh][n][f]
// ---------------------------------------------------------------------------
__global__ void transpose_kernel(const float* __restrict__ feats) {
    __shared__ float tile[32][33];
    const int bh = blockIdx.y;
    const int n0 = blockIdx.x * 32;
    const int tx = threadIdx.x, ty = threadIdx.y;
    tile[ty][tx] = feats[(bh * FD + ty) * NN + n0 + tx];    // coalesced in n
    __syncthreads();
    g_featsT[(bh * NN + n0 + ty) * FD + tx] = tile[tx][ty]; // coalesced in f
}

// ---------------------------------------------------------------------------
// 2) scatter into fixed-capacity buckets, 2 entries per thread
// ---------------------------------------------------------------------------
__global__ void scatter_kernel(const float* __restrict__ lc,
                               const int* __restrict__ fidx) {
    int t = blockIdx.x * blockDim.x + threadIdx.x;
    int i0 = t * 2;                                   // 0..NE_TOT-1, step 2
    int2   cc = ((const int2*)fidx)[t];
    float2 ll = ((const float2*)lc)[t];
#pragma unroll
    for (int k = 0; k < 2; k++) {
        int i  = i0 + k;
        int bh = i / NE;
        int n  = i & (NN - 1);
        int c  = (k ? cc.y : cc.x) & (NC - 1);
        float l = k ? ll.y : ll.x;
        int bhc = bh * NC + c;
        int pos = atomicAdd(&g_count[bhc], 1);
        if (pos < KCAP) {
            g_entries[bhc * KCAP + pos] = make_uint2((unsigned)n, __float_as_uint(l));
        } else {
            int sp = atomicAdd(&g_spill_cnt, 1);
            if (sp < SPILL_CAP)
                g_spill[sp] = make_uint4((unsigned)bh, (unsigned)c,
                                         (unsigned)n, __float_as_uint(l));
        }
    }
}

// ---------------------------------------------------------------------------
// 3) gather: block = 64 cells. Phase 1: cooperative coalesced load of all
//    entry slots + counts into smem. Phase 2: warp w handles cells w and
//    w+32 (lane = feature); entries via broadcast LDS -> independent LDGs.
//    Phase 3: staged coalesced output.
// grid (NC/CPB, BH), block 1024
// ---------------------------------------------------------------------------
__global__ void gather_kernel(float* __restrict__ out) {
    __shared__ uint2 s_ent[CPB * KCAP];     // 4 KB
    __shared__ int   s_cnt[CPB];
    __shared__ float s_tile[FD][CPB + 1];   // ~8.3 KB

    const int bh = blockIdx.y;
    const int c0 = blockIdx.x * CPB;
    const int t  = threadIdx.x;

    // Phase 1: bulk load (fully coalesced, high MLP)
    if (t < CPB * KCAP)                              // 512 threads
        s_ent[t] = g_entries[(bh * NC + c0) * KCAP + t];
    else if (t < CPB * KCAP + CPB)                   // 64 threads
        s_cnt[t - CPB * KCAP] = g_count[bh * NC + c0 + (t - CPB * KCAP)];
    __syncthreads();

    // Phase 2: warp per cell, 2 cells per warp
    const int lane = t & 31;      // = f
    const int w    = t >> 5;
    const float* __restrict__ ft = g_featsT + (size_t)bh * NN * FD;

#pragma unroll
    for (int half = 0; half < 2; half++) {
        const int cell = w + half * 32;
        const int cnt  = min(s_cnt[cell], KCAP);
        const uint2* __restrict__ ep = &s_ent[cell * KCAP];
        float m = 0.f;
#pragma unroll
        for (int j = 0; j < KCAP; j++) {
            if (j < cnt) {
                const uint2 e = ep[j];                       // broadcast LDS
                const float fv = ft[e.x * FD + lane];        // 128B row, L2
                m = fmaxf(m, fv * __uint_as_float(e.y));
            }
        }
        s_tile[lane][cell] = m;
    }
    __syncthreads();

    // Phase 3: coalesced write: thread t -> (f = t/CPB, cl = t%CPB), 2 rounds
#pragma unroll
    for (int r = 0; r < 2; r++) {
        const int idx = t + r * 1024;
        const int f   = idx >> 6;          // /CPB
        const int cl  = idx & (CPB - 1);
        out[((size_t)bh * FD + f) * NC + c0 + cl] = s_tile[f][cl];
    }
}

// ---------------------------------------------------------------------------
// 4) spill: overflow entries -> atomicMax into out (after gather)
// grid 64 x 256; warp per entry, lane = f
// ---------------------------------------------------------------------------
__global__ void spill_kernel(float* __restrict__ out) {
    const int lane = threadIdx.x & 31;
    const int wid  = (blockIdx.x * blockDim.x + threadIdx.x) >> 5;
    const int nw   = (gridDim.x * blockDim.x) >> 5;
    const int cnt  = min(g_spill_cnt, SPILL_CAP);
    for (int s = wid; s < cnt; s += nw) {
        uint4 e = g_spill[s];
        const int bh = (int)e.x, c = (int)e.y, n = (int)e.z;
        const float l = __uint_as_float(e.w);
        const float fv = g_featsT[((size_t)bh * NN + n) * FD + lane];
        const float val = fv * l;
        if (val > 0.f)
            atomicMax((int*)out + ((size_t)bh * FD + lane) * NC + c,
                      __float_as_int(val));
    }
}

// ---------------------------------------------------------------------------
// kernel_launch
//   d_in[0] local_coordinate  float32 [B,H,V,N]
//   d_in[1] flattened_index   int32   [B,H,V,N]
//   d_in[2] features          float32 [B,128,N]
//   d_out   float32 [B,128,32,32,32]
// ---------------------------------------------------------------------------
extern "C" void kernel_launch(void* const* d_in, const int* in_sizes, int n_in,
                              void* d_out, int out_size) {
    const float* lc    = (const float*)d_in[0];
    const int*   fidx  = (const int*)d_in[1];
    const float* feats = (const float*)d_in[2];
    float*       out   = (float*)d_out;

    // 0) zero counters: BH*NC ints = 524288 -> 131072 int4
    zero_counts_kernel<<<(BH * NC / 4) / 256, 256>>>();

    // 1) transpose feats
    {
        dim3 block(32, 32), grid(NN / 32, BH);
        transpose_kernel<<<grid, block>>>(feats);
    }

    // 2) scatter into buckets (2 entries per thread)
    scatter_kernel<<<(NE_TOT / 2) / 256, 256>>>(lc, fidx);

    // 3) gather -> out (writes every cell)
    {
        dim3 grid(NC / CPB, BH);
        gather_kernel<<<grid, 1024>>>(out);
    }

    // 4) spills
    spill_kernel<<<64, 256>>>(out);
}